// round 11
// baseline (speedup 1.0000x reference)
#include <cuda_runtime.h>
#include <cstdint>
#include <math.h>

// Problem constants
#define T_TOK 4096      // B*S
#define HDIM  1024
#define IDIM  2816
#define EDIM  8
#define TOPK  2
#define NPAIR (T_TOK*TOPK)   // 8192

#define KC    32        // K-chunk per stage
#define BMT   128       // CTA M tile
#define BNT   128       // CTA N tile
#define PADA  36        // A smem row pitch (floats)
#define PADB  136       // B smem row pitch (floats)
#define A_FL  (BMT*PADA)   // 4608 floats
#define B_FL  (KC*PADB)    // 4352 floats
#define STAGE_FL (A_FL + B_FL)

// ---------------- scratch (__device__ globals: alloc-free) ----------------
__device__ int   g_cnt[EDIM];        // zero-init at load; scan re-zeroes each call
__device__ int   g_off[EDIM + 1];
__device__ int   g_fill[EDIM];
__device__ int   g_tok_e[NPAIR];
__device__ float g_tok_w[NPAIR];
__device__ int   g_list[NPAIR];
__device__ float g_wt[NPAIR];
__device__ int   g_tokpair[NPAIR];
__device__ float g_raw[(size_t)NPAIR * IDIM];      // raw gate GEMM out, 92.3 MB
__device__ float g_act[(size_t)NPAIR * IDIM];      // swiglu activations, 92.3 MB
__device__ float g_pairout[(size_t)NPAIR * HDIM];  // 33.5 MB

// ---------------- helpers ----------------
__device__ __forceinline__ uint32_t f2tf32(float f) {
    uint32_t r;
    asm("cvt.rna.tf32.f32 %0, %1;" : "=r"(r) : "f"(f));
    return r;
}
__device__ __forceinline__ float tf32f(float f) {
    return __uint_as_float(f2tf32(f));
}
__device__ __forceinline__ void mma_tf32(float* d, const uint32_t* a, const uint32_t* b) {
    asm volatile(
        "mma.sync.aligned.m16n8k8.row.col.f32.tf32.tf32.f32 "
        "{%0,%1,%2,%3}, {%4,%5,%6,%7}, {%8,%9}, {%0,%1,%2,%3};"
        : "+f"(d[0]), "+f"(d[1]), "+f"(d[2]), "+f"(d[3])
        : "r"(a[0]), "r"(a[1]), "r"(a[2]), "r"(a[3]), "r"(b[0]), "r"(b[1]));
}

// ---------------- routing kernels ----------------
__global__ void router_kernel(const float* __restrict__ x,
                              const float* __restrict__ gw,
                              float* __restrict__ out_logits) {
    const int t = blockIdx.x;
    const int tid = threadIdx.x;
    float acc[EDIM];
#pragma unroll
    for (int e = 0; e < EDIM; e++) acc[e] = 0.f;
    const float* xr = x + (size_t)t * HDIM;
    for (int h = tid; h < HDIM; h += 128) {
        float xv = xr[h];
        const float* gr = gw + (size_t)h * EDIM;
#pragma unroll
        for (int e = 0; e < EDIM; e++) acc[e] += xv * gr[e];
    }
    __shared__ float red[EDIM][128];
#pragma unroll
    for (int e = 0; e < EDIM; e++) red[e][tid] = acc[e];
    __syncthreads();
    for (int s = 64; s > 0; s >>= 1) {
        if (tid < s) {
#pragma unroll
            for (int e = 0; e < EDIM; e++) red[e][tid] += red[e][tid + s];
        }
        __syncthreads();
    }
    if (tid == 0) {
        float l[EDIM];
#pragma unroll
        for (int e = 0; e < EDIM; e++) {
            l[e] = red[e][0];
            out_logits[(size_t)t * EDIM + e] = l[e];
        }
        int i0 = 0;
#pragma unroll
        for (int e = 1; e < EDIM; e++) if (l[e] > l[i0]) i0 = e;
        int i1 = -1;
#pragma unroll
        for (int e = 0; e < EDIM; e++) {
            if (e == i0) continue;
            if (i1 < 0 || l[e] > l[i1]) i1 = e;
        }
        float e1 = expf(l[i1] - l[i0]);
        float w0 = 1.f / (1.f + e1);
        float w1 = e1 / (1.f + e1);
        g_tok_e[t * 2 + 0] = i0; g_tok_w[t * 2 + 0] = w0;
        g_tok_e[t * 2 + 1] = i1; g_tok_w[t * 2 + 1] = w1;
        atomicAdd(&g_cnt[i0], 1);
        atomicAdd(&g_cnt[i1], 1);
    }
}

__global__ void scan_kernel() {
    int s = 0;
    for (int e = 0; e < EDIM; e++) {
        g_off[e] = s;
        s += g_cnt[e];
        g_fill[e] = 0;
        g_cnt[e] = 0;
    }
    g_off[EDIM] = s;
}

__global__ void assign_kernel() {
    int t = blockIdx.x * blockDim.x + threadIdx.x;
    if (t >= T_TOK) return;
#pragma unroll
    for (int k = 0; k < TOPK; k++) {
        int e = g_tok_e[t * 2 + k];
        int slot = atomicAdd(&g_fill[e], 1);
        int p = g_off[e] + slot;
        g_list[p] = t;
        g_wt[p] = g_tok_w[t * 2 + k];
        g_tokpair[t * 2 + k] = p;
    }
}

// ============================================================================
// GEMM mainloop core: double-buffered smem, ONE sync per k-chunk.
// Per iteration: LDG(kc+1) -> compute(kc) -> STS(kc+1 into other buffer) -> sync.
// bptr points at W + n0 (tile row 0); per-thread offsets applied inside.
// ============================================================================
struct GemmCore {
    static __device__ __forceinline__ void run(
        float* sbuf,
        const float* aptr[4], const float* bptr, size_t ldb,
        int NCH, int tid, int wid, int lane,
        float acc[4][4][4]) {
        const int ac4 = (tid & 7) * 4;
        const int ar  = tid >> 3;            // 0..31
        const int bc4 = (tid & 31) * 4;
        const int br  = tid >> 5;            // 0..7
        const int m0w = (wid >> 2) * 64;
        const int n0w = (wid & 3) * 32;
        const int r0 = lane >> 2;
        const int kq = lane & 3;
        const int nq = lane >> 2;

        const float* bp = bptr + (size_t)br * ldb + bc4;

        float* sA[2] = { sbuf,            sbuf + STAGE_FL };
        float* sB[2] = { sbuf + A_FL,     sbuf + STAGE_FL + A_FL };

        float4 va[4], vb[4];
        // prologue: load + stage chunk 0
#pragma unroll
        for (int i = 0; i < 4; i++) {
            va[i] = *(const float4*)(aptr[i]);
            vb[i] = *(const float4*)(bp + (size_t)(i * 8) * ldb);
        }
#pragma unroll
        for (int i = 0; i < 4; i++) {
            float* da = sA[0] + (i * 32 + ar) * PADA + ac4;
            da[0] = tf32f(va[i].x); da[1] = tf32f(va[i].y);
            da[2] = tf32f(va[i].z); da[3] = tf32f(va[i].w);
            float* db = sB[0] + (i * 8 + br) * PADB + bc4;
            db[0] = tf32f(vb[i].x); db[1] = tf32f(vb[i].y);
            db[2] = tf32f(vb[i].z); db[3] = tf32f(vb[i].w);
        }
        __syncthreads();

#pragma unroll 1
        for (int kc = 0; kc < NCH; kc++) {
            const int buf = kc & 1;
            const bool more = (kc + 1 < NCH);
            // issue next-chunk LDGs; latency hides under compute below
            if (more) {
                const int k0n = (kc + 1) * KC;
                const float* bn = bp + (size_t)k0n * ldb;
#pragma unroll
                for (int i = 0; i < 4; i++) {
                    va[i] = *(const float4*)(aptr[i] + k0n);
                    vb[i] = *(const float4*)(bn + (size_t)(i * 8) * ldb);
                }
            }
            // compute on current buffer
            const float* cA = sA[buf];
            const float* cB = sB[buf];
#pragma unroll
            for (int k8 = 0; k8 < KC; k8 += 8) {
                uint32_t af[4][4];
#pragma unroll
                for (int mt = 0; mt < 4; mt++) {
                    const float* ab = cA + (m0w + mt * 16 + r0) * PADA + k8 + kq;
                    af[mt][0] = __float_as_uint(ab[0]);
                    af[mt][1] = __float_as_uint(ab[8 * PADA]);
                    af[mt][2] = __float_as_uint(ab[4]);
                    af[mt][3] = __float_as_uint(ab[8 * PADA + 4]);
                }
#pragma unroll
                for (int nt = 0; nt < 4; nt++) {
                    const float* bb = cB + (k8 + kq) * PADB + n0w + nt * 8 + nq;
                    uint32_t bf[2] = { __float_as_uint(bb[0]), __float_as_uint(bb[4 * PADB]) };
#pragma unroll
                    for (int mt = 0; mt < 4; mt++)
                        mma_tf32(acc[mt][nt], af[mt], bf);
                }
            }
            // stage next chunk into the other buffer (no reader hazard:
            // previous-iteration sync drained all reads of that buffer)
            if (more) {
                float* dA = sA[buf ^ 1];
                float* dB = sB[buf ^ 1];
#pragma unroll
                for (int i = 0; i < 4; i++) {
                    float* da = dA + (i * 32 + ar) * PADA + ac4;
                    da[0] = tf32f(va[i].x); da[1] = tf32f(va[i].y);
                    da[2] = tf32f(va[i].z); da[3] = tf32f(va[i].w);
                    float* db = dB + (i * 8 + br) * PADB + bc4;
                    db[0] = tf32f(vb[i].x); db[1] = tf32f(vb[i].y);
                    db[2] = tf32f(vb[i].z); db[3] = tf32f(vb[i].w);
                }
            }
            __syncthreads();
        }
    }
};

#define GEMM_SMEM ((128 + 2 * STAGE_FL) * 4)   // rowtok + double-buffered A|B

// ---------------- gate GEMM: g_raw = x[rowtok] @ Wg ----------------
__global__ __launch_bounds__(256, 2) void gate_tc(
    const float* __restrict__ x, const float* __restrict__ Wg) {
    extern __shared__ float sm[];
    const int e = blockIdx.z;
    const int ne = g_off[e + 1] - g_off[e];
    const int m0 = blockIdx.y * BMT;
    if (m0 >= ne) return;
    const int n0 = blockIdx.x * BNT;
    const int off = g_off[e];

    int* rowtok = (int*)sm;
    const int tid = threadIdx.x;
    const int wid = tid >> 5;
    const int lane = tid & 31;
    if (tid < BMT) {
        int m = m0 + tid;
        rowtok[tid] = g_list[off + (m < ne ? m : 0)];
    }
    __syncthreads();

    const float* aptr[4];
#pragma unroll
    for (int i = 0; i < 4; i++) {
        int r = i * 32 + (tid >> 3);
        aptr[i] = x + (size_t)rowtok[r] * HDIM + (tid & 7) * 4;
    }
    const float* bptr = Wg + (size_t)e * HDIM * IDIM + n0;

    float acc[4][4][4];
#pragma unroll
    for (int i = 0; i < 4; i++)
#pragma unroll
        for (int j = 0; j < 4; j++)
#pragma unroll
            for (int q = 0; q < 4; q++) acc[i][j][q] = 0.f;

    GemmCore::run(sm + 128, aptr, bptr, IDIM, HDIM / KC, tid, wid, lane, acc);

    const int m0w = (wid >> 2) * 64;
    const int n0w = (wid & 3) * 32;
#pragma unroll
    for (int mt = 0; mt < 4; mt++) {
        int rloc = m0w + mt * 16 + (lane >> 2);
#pragma unroll
        for (int h = 0; h < 2; h++) {
            int m = m0 + rloc + h * 8;
            if (m < ne) {
                float* orow = g_raw + (size_t)(off + m) * IDIM + n0;
#pragma unroll
                for (int nt = 0; nt < 4; nt++) {
                    int c = n0w + nt * 8 + 2 * (lane & 3);
                    float2 v;
                    v.x = acc[mt][nt][2 * h];
                    v.y = acc[mt][nt][2 * h + 1];
                    *(float2*)(orow + c) = v;
                }
            }
        }
    }
}

// ---------------- up GEMM + SwiGLU: g_act = silu(g_raw) * (x @ Wu) ----------
__global__ __launch_bounds__(256, 2) void up_tc(
    const float* __restrict__ x, const float* __restrict__ Wu) {
    extern __shared__ float sm[];
    const int e = blockIdx.z;
    const int ne = g_off[e + 1] - g_off[e];
    const int m0 = blockIdx.y * BMT;
    if (m0 >= ne) return;
    const int n0 = blockIdx.x * BNT;
    const int off = g_off[e];

    int* rowtok = (int*)sm;
    const int tid = threadIdx.x;
    const int wid = tid >> 5;
    const int lane = tid & 31;
    if (tid < BMT) {
        int m = m0 + tid;
        rowtok[tid] = g_list[off + (m < ne ? m : 0)];
    }
    __syncthreads();

    const float* aptr[4];
#pragma unroll
    for (int i = 0; i < 4; i++) {
        int r = i * 32 + (tid >> 3);
        aptr[i] = x + (size_t)rowtok[r] * HDIM + (tid & 7) * 4;
    }
    const float* bptr = Wu + (size_t)e * HDIM * IDIM + n0;

    float acc[4][4][4];
#pragma unroll
    for (int i = 0; i < 4; i++)
#pragma unroll
        for (int j = 0; j < 4; j++)
#pragma unroll
            for (int q = 0; q < 4; q++) acc[i][j][q] = 0.f;

    GemmCore::run(sm + 128, aptr, bptr, IDIM, HDIM / KC, tid, wid, lane, acc);

    const int m0w = (wid >> 2) * 64;
    const int n0w = (wid & 3) * 32;
#pragma unroll
    for (int mt = 0; mt < 4; mt++) {
        int rloc = m0w + mt * 16 + (lane >> 2);
#pragma unroll
        for (int h = 0; h < 2; h++) {
            int m = m0 + rloc + h * 8;
            if (m < ne) {
                const float* grow = g_raw + (size_t)(off + m) * IDIM + n0;
                float* orow = g_act + (size_t)(off + m) * IDIM + n0;
#pragma unroll
                for (int nt = 0; nt < 4; nt++) {
                    int c = n0w + nt * 8 + 2 * (lane & 3);
                    float2 gv = *(const float2*)(grow + c);
                    float2 v;
                    v.x = gv.x / (1.f + expf(-gv.x)) * acc[mt][nt][2 * h];
                    v.y = gv.y / (1.f + expf(-gv.y)) * acc[mt][nt][2 * h + 1];
                    *(float2*)(orow + c) = v;
                }
            }
        }
    }
}

// ---------------- down GEMM: g_pairout = wt * (g_act @ Wd) ----------------
__global__ __launch_bounds__(256, 2) void down_tc(const float* __restrict__ Wd) {
    extern __shared__ float sm[];
    const int e = blockIdx.z;
    const int ne = g_off[e + 1] - g_off[e];
    const int m0 = blockIdx.y * BMT;
    if (m0 >= ne) return;
    const int n0 = blockIdx.x * BNT;
    const int off = g_off[e];

    const int tid = threadIdx.x;
    const int wid = tid >> 5;
    const int lane = tid & 31;

    const float* aptr[4];
#pragma unroll
    for (int i = 0; i < 4; i++) {
        int r = i * 32 + (tid >> 3);
        int idx = off + m0 + r;
        if (idx >= NPAIR) idx = NPAIR - 1;
        aptr[i] = g_act + (size_t)idx * IDIM + (tid & 7) * 4;
    }
    const float* bptr = Wd + (size_t)e * IDIM * HDIM + n0;

    float acc[4][4][4];
#pragma unroll
    for (int i = 0; i < 4; i++)
#pragma unroll
        for (int j = 0; j < 4; j++)
#pragma unroll
            for (int q = 0; q < 4; q++) acc[i][j][q] = 0.f;

    GemmCore::run(sm + 128, aptr, bptr, HDIM, IDIM / KC, tid, wid, lane, acc);

    const int m0w = (wid >> 2) * 64;
    const int n0w = (wid & 3) * 32;
#pragma unroll
    for (int mt = 0; mt < 4; mt++) {
        int rloc = m0w + mt * 16 + (lane >> 2);
#pragma unroll
        for (int h = 0; h < 2; h++) {
            int m = m0 + rloc + h * 8;
            if (m < ne) {
                float wt = g_wt[off + m];
                float* orow = g_pairout + (size_t)(off + m) * HDIM + n0;
#pragma unroll
                for (int nt = 0; nt < 4; nt++) {
                    int c = n0w + nt * 8 + 2 * (lane & 3);
                    float2 v;
                    v.x = wt * acc[mt][nt][2 * h];
                    v.y = wt * acc[mt][nt][2 * h + 1];
                    *(float2*)(orow + c) = v;
                }
            }
        }
    }
}

// out[t, :] = pairout[p0, :] + pairout[p1, :]
__global__ void combine_kernel(float* __restrict__ out) {
    int idx = blockIdx.x * blockDim.x + threadIdx.x;
    int t = idx >> 8;
    int h4 = idx & 255;
    int p0 = g_tokpair[t * 2 + 0];
    int p1 = g_tokpair[t * 2 + 1];
    const float4* po = (const float4*)g_pairout;
    float4 a = po[(size_t)p0 * 256 + h4];
    float4 b = po[(size_t)p1 * 256 + h4];
    float4 r;
    r.x = a.x + b.x; r.y = a.y + b.y; r.z = a.z + b.z; r.w = a.w + b.w;
    ((float4*)out)[idx] = r;
}

// ---------------- launch ----------------
extern "C" void kernel_launch(void* const* d_in, const int* in_sizes, int n_in,
                              void* d_out, int out_size) {
    const float* x  = (const float*)d_in[0];
    const float* gw = (const float*)d_in[1];
    const float* Wg = (const float*)d_in[2];
    const float* Wu = (const float*)d_in[3];
    const float* Wd = (const float*)d_in[4];
    float* out = (float*)d_out;
    float* out_logits = out + (size_t)T_TOK * HDIM;

    cudaFuncSetAttribute(gate_tc, cudaFuncAttributeMaxDynamicSharedMemorySize, GEMM_SMEM);
    cudaFuncSetAttribute(up_tc, cudaFuncAttributeMaxDynamicSharedMemorySize, GEMM_SMEM);
    cudaFuncSetAttribute(down_tc, cudaFuncAttributeMaxDynamicSharedMemorySize, GEMM_SMEM);

    router_kernel<<<T_TOK, 128>>>(x, gw, out_logits);
    scan_kernel<<<1, 1>>>();
    assign_kernel<<<T_TOK / 256, 256>>>();
    gate_tc<<<dim3(IDIM / BNT, NPAIR / BMT, EDIM), 256, GEMM_SMEM>>>(x, Wg);
    up_tc<<<dim3(IDIM / BNT, NPAIR / BMT, EDIM), 256, GEMM_SMEM>>>(x, Wu);
    down_tc<<<dim3(HDIM / BNT, NPAIR / BMT, EDIM), 256, GEMM_SMEM>>>(Wd);
    combine_kernel<<<(T_TOK * HDIM / 4) / 256, 256>>>(out);
}

// round 13
// speedup vs baseline: 1.2056x; 1.2056x over previous
#include <cuda_runtime.h>
#include <cstdint>
#include <math.h>

// Problem constants
#define T_TOK 4096      // B*S
#define HDIM  1024
#define IDIM  2816
#define EDIM  8
#define TOPK  2
#define NPAIR (T_TOK*TOPK)   // 8192

#define KC    32        // K-chunk per stage
#define BMT   128       // CTA M tile
#define BNT   128       // CTA N tile
#define PADA  36        // A smem row pitch (floats)
#define PADB  136       // B smem row pitch (floats)
#define A_FL  (BMT*PADA)   // 4608 floats
#define B_FL  (KC*PADB)    // 4352 floats
#define STAGE_FL (A_FL + B_FL)

// weight rounding (fused into router launch)
#define W_ELEMS (EDIM*HDIM*IDIM)        // 23,068,672 (same for Wg/Wu/Wd)
#define W_Q (W_ELEMS/4)                 // 5,767,168 float4s
#define RQ_PER_BLK (128*8)              // 1024 float4 per block
#define RBLKS_PER_W ((W_Q + RQ_PER_BLK - 1)/RQ_PER_BLK)   // 5632
#define RBLKS (3*RBLKS_PER_W)           // 16896

// ---------------- scratch (__device__ globals: alloc-free) ----------------
__device__ int   g_cnt[EDIM];
__device__ int   g_off[EDIM + 1];
__device__ int   g_fill[EDIM];
__device__ int   g_tok_e[NPAIR];
__device__ float g_tok_w[NPAIR];
__device__ int   g_list[NPAIR];
__device__ float g_wt[NPAIR];
__device__ int   g_tokpair[NPAIR];
__device__ float g_raw[(size_t)NPAIR * IDIM];      // raw gate GEMM out
__device__ float g_act[(size_t)NPAIR * IDIM];      // swiglu activations
__device__ float g_pairout[(size_t)NPAIR * HDIM];
__device__ float g_wgr[(size_t)W_ELEMS];           // tf32-rounded Wg
__device__ float g_wur[(size_t)W_ELEMS];           // tf32-rounded Wu
__device__ float g_wdr[(size_t)W_ELEMS];           // tf32-rounded Wd

// ---------------- helpers ----------------
__device__ __forceinline__ uint32_t f2tf32(float f) {
    uint32_t r;
    asm("cvt.rna.tf32.f32 %0, %1;" : "=r"(r) : "f"(f));
    return r;
}
__device__ __forceinline__ float tf32f(float f) {
    return __uint_as_float(f2tf32(f));
}
__device__ __forceinline__ void mma_tf32(float* d, const uint32_t* a, const uint32_t* b) {
    asm volatile(
        "mma.sync.aligned.m16n8k8.row.col.f32.tf32.tf32.f32 "
        "{%0,%1,%2,%3}, {%4,%5,%6,%7}, {%8,%9}, {%0,%1,%2,%3};"
        : "+f"(d[0]), "+f"(d[1]), "+f"(d[2]), "+f"(d[3])
        : "r"(a[0]), "r"(a[1]), "r"(a[2]), "r"(a[3]), "r"(b[0]), "r"(b[1]));
}
__device__ __forceinline__ uint32_t smem_u32(const void* p) {
    uint32_t a;
    asm("{ .reg .u64 t; cvta.to.shared.u64 t, %1; cvt.u32.u64 %0, t; }" : "=r"(a) : "l"(p));
    return a;
}
__device__ __forceinline__ void cp16(uint32_t dst, const void* src) {
    asm volatile("cp.async.ca.shared.global [%0], [%1], 16;" :: "r"(dst), "l"(src));
}
#define CP_COMMIT() asm volatile("cp.async.commit_group;" ::: "memory")
#define CP_WAIT0()  asm volatile("cp.async.wait_group 0;" ::: "memory")

// ---------------- router + weight pre-rounding (fused launch #1) ----------
__global__ void router_kernel(const float* __restrict__ x,
                              const float* __restrict__ gw,
                              const float* __restrict__ Wg,
                              const float* __restrict__ Wu,
                              const float* __restrict__ Wd,
                              float* __restrict__ out_logits) {
    if (blockIdx.x >= T_TOK) {
        // weight pre-rounding duty
        int rb = blockIdx.x - T_TOK;
        int w = rb / RBLKS_PER_W;
        int b = rb % RBLKS_PER_W;
        const float4* src = (w == 0) ? (const float4*)Wg
                          : (w == 1) ? (const float4*)Wu
                                     : (const float4*)Wd;
        float4* dst = (w == 0) ? (float4*)g_wgr
                    : (w == 1) ? (float4*)g_wur
                               : (float4*)g_wdr;
        int base = b * RQ_PER_BLK + threadIdx.x;
#pragma unroll
        for (int it = 0; it < 8; it++) {
            int i = base + it * 128;
            if (i < W_Q) {
                float4 v = src[i];
                v.x = tf32f(v.x); v.y = tf32f(v.y);
                v.z = tf32f(v.z); v.w = tf32f(v.w);
                dst[i] = v;
            }
        }
        return;
    }

    const int t = blockIdx.x;
    const int tid = threadIdx.x;
    float acc[EDIM];
#pragma unroll
    for (int e = 0; e < EDIM; e++) acc[e] = 0.f;
    const float* xr = x + (size_t)t * HDIM;
    for (int h = tid; h < HDIM; h += 128) {
        float xv = xr[h];
        const float* gr = gw + (size_t)h * EDIM;
#pragma unroll
        for (int e = 0; e < EDIM; e++) acc[e] += xv * gr[e];
    }
    __shared__ float red[EDIM][128];
#pragma unroll
    for (int e = 0; e < EDIM; e++) red[e][tid] = acc[e];
    __syncthreads();
    for (int s = 64; s > 0; s >>= 1) {
        if (tid < s) {
#pragma unroll
            for (int e = 0; e < EDIM; e++) red[e][tid] += red[e][tid + s];
        }
        __syncthreads();
    }
    if (tid == 0) {
        float l[EDIM];
#pragma unroll
        for (int e = 0; e < EDIM; e++) {
            l[e] = red[e][0];
            out_logits[(size_t)t * EDIM + e] = l[e];
        }
        int i0 = 0;
#pragma unroll
        for (int e = 1; e < EDIM; e++) if (l[e] > l[i0]) i0 = e;
        int i1 = -1;
#pragma unroll
        for (int e = 0; e < EDIM; e++) {
            if (e == i0) continue;
            if (i1 < 0 || l[e] > l[i1]) i1 = e;
        }
        float e1 = expf(l[i1] - l[i0]);
        float w0 = 1.f / (1.f + e1);
        float w1 = e1 / (1.f + e1);
        g_tok_e[t * 2 + 0] = i0; g_tok_w[t * 2 + 0] = w0;
        g_tok_e[t * 2 + 1] = i1; g_tok_w[t * 2 + 1] = w1;
        atomicAdd(&g_cnt[i0], 1);
        atomicAdd(&g_cnt[i1], 1);
    }
}

__global__ void scan_kernel() {
    int s = 0;
    for (int e = 0; e < EDIM; e++) {
        g_off[e] = s;
        s += g_cnt[e];
        g_fill[e] = 0;
        g_cnt[e] = 0;
    }
    g_off[EDIM] = s;
}

__global__ void assign_kernel() {
    int t = blockIdx.x * blockDim.x + threadIdx.x;
    if (t >= T_TOK) return;
#pragma unroll
    for (int k = 0; k < TOPK; k++) {
        int e = g_tok_e[t * 2 + k];
        int slot = atomicAdd(&g_fill[e], 1);
        int p = g_off[e] + slot;
        g_list[p] = t;
        g_wt[p] = g_tok_w[t * 2 + k];
        g_tokpair[t * 2 + k] = p;
    }
}

// ============================================================================
// GEMM mainloop core: double-buffered smem, ONE sync per k-chunk.
// B (pre-rounded weights) streamed via cp.async (zero register cost).
// A staged via LDG->cvt->STS with a 16-reg float4 prefetch.
// bptr points at Wrounded + n0 (tile row 0).
// ============================================================================
struct GemmCore {
    static __device__ __forceinline__ void run(
        float* sbuf,
        const float* aptr[4], const float* bptr, size_t ldb,
        int NCH, int tid, int wid, int lane,
        float acc[4][4][4]) {
        const int ac4 = (tid & 7) * 4;
        const int ar  = tid >> 3;            // 0..31
        const int bc4 = (tid & 31) * 4;
        const int br  = tid >> 5;            // 0..7
        const int m0w = (wid >> 2) * 64;
        const int n0w = (wid & 3) * 32;
        const int r0 = lane >> 2;
        const int kq = lane & 3;
        const int nq = lane >> 2;

        const float* bp = bptr + (size_t)br * ldb + bc4;

        float* sA[2] = { sbuf,        sbuf + STAGE_FL };
        float* sB[2] = { sbuf + A_FL, sbuf + STAGE_FL + A_FL };
        const uint32_t su = smem_u32(sbuf);
        const uint32_t sBu[2] = { su + A_FL * 4, su + (STAGE_FL + A_FL) * 4 };
        const uint32_t boff = ((uint32_t)br * PADB + bc4) * 4;

        float4 va[4];
        // prologue: chunk 0
#pragma unroll
        for (int i = 0; i < 4; i++)
            cp16(sBu[0] + boff + (uint32_t)(i * 8 * PADB * 4), bp + (size_t)(i * 8) * ldb);
        CP_COMMIT();
#pragma unroll
        for (int i = 0; i < 4; i++) va[i] = *(const float4*)(aptr[i]);
#pragma unroll
        for (int i = 0; i < 4; i++) {
            float* da = sA[0] + (i * 32 + ar) * PADA + ac4;
            da[0] = tf32f(va[i].x); da[1] = tf32f(va[i].y);
            da[2] = tf32f(va[i].z); da[3] = tf32f(va[i].w);
        }
        CP_WAIT0();
        __syncthreads();

#pragma unroll 1
        for (int kc = 0; kc < NCH; kc++) {
            const int buf = kc & 1;
            const bool more = (kc + 1 < NCH);
            if (more) {
                const int k0n = (kc + 1) * KC;
                const float* bn = bp + (size_t)k0n * ldb;
#pragma unroll
                for (int i = 0; i < 4; i++)
                    cp16(sBu[buf ^ 1] + boff + (uint32_t)(i * 8 * PADB * 4),
                         bn + (size_t)(i * 8) * ldb);
                CP_COMMIT();
#pragma unroll
                for (int i = 0; i < 4; i++) va[i] = *(const float4*)(aptr[i] + k0n);
            }
            // compute on current buffer
            const float* cA = sA[buf];
            const float* cB = sB[buf];
#pragma unroll
            for (int k8 = 0; k8 < KC; k8 += 8) {
                uint32_t af[4][4];
#pragma unroll
                for (int mt = 0; mt < 4; mt++) {
                    const float* ab = cA + (m0w + mt * 16 + r0) * PADA + k8 + kq;
                    af[mt][0] = __float_as_uint(ab[0]);
                    af[mt][1] = __float_as_uint(ab[8 * PADA]);
                    af[mt][2] = __float_as_uint(ab[4]);
                    af[mt][3] = __float_as_uint(ab[8 * PADA + 4]);
                }
#pragma unroll
                for (int nt = 0; nt < 4; nt++) {
                    const float* bb = cB + (k8 + kq) * PADB + n0w + nt * 8 + nq;
                    uint32_t bf[2] = { __float_as_uint(bb[0]), __float_as_uint(bb[4 * PADB]) };
#pragma unroll
                    for (int mt = 0; mt < 4; mt++)
                        mma_tf32(acc[mt][nt], af[mt], bf);
                }
            }
            // stage next A chunk into the other buffer; wait for its B cp.async
            if (more) {
                float* dA = sA[buf ^ 1];
#pragma unroll
                for (int i = 0; i < 4; i++) {
                    float* da = dA + (i * 32 + ar) * PADA + ac4;
                    da[0] = tf32f(va[i].x); da[1] = tf32f(va[i].y);
                    da[2] = tf32f(va[i].z); da[3] = tf32f(va[i].w);
                }
                CP_WAIT0();
            }
            __syncthreads();
        }
    }
};

#define GEMM_SMEM ((128 + 2 * STAGE_FL) * 4)   // rowtok + double-buffered A|B

// ---------------- gate GEMM: g_raw = x[rowtok] @ Wg ----------------
__global__ __launch_bounds__(256, 2) void gate_tc(const float* __restrict__ x) {
    extern __shared__ float sm[];
    const int e = blockIdx.z;
    const int ne = g_off[e + 1] - g_off[e];
    const int m0 = blockIdx.y * BMT;
    if (m0 >= ne) return;
    const int n0 = blockIdx.x * BNT;
    const int off = g_off[e];

    int* rowtok = (int*)sm;
    const int tid = threadIdx.x;
    const int wid = tid >> 5;
    const int lane = tid & 31;
    if (tid < BMT) {
        int m = m0 + tid;
        rowtok[tid] = g_list[off + (m < ne ? m : 0)];
    }
    __syncthreads();

    const float* aptr[4];
#pragma unroll
    for (int i = 0; i < 4; i++) {
        int r = i * 32 + (tid >> 3);
        aptr[i] = x + (size_t)rowtok[r] * HDIM + (tid & 7) * 4;
    }
    const float* bptr = g_wgr + (size_t)e * HDIM * IDIM + n0;

    float acc[4][4][4];
#pragma unroll
    for (int i = 0; i < 4; i++)
#pragma unroll
        for (int j = 0; j < 4; j++)
#pragma unroll
            for (int q = 0; q < 4; q++) acc[i][j][q] = 0.f;

    GemmCore::run(sm + 128, aptr, bptr, IDIM, HDIM / KC, tid, wid, lane, acc);

    const int m0w = (wid >> 2) * 64;
    const int n0w = (wid & 3) * 32;
#pragma unroll
    for (int mt = 0; mt < 4; mt++) {
        int rloc = m0w + mt * 16 + (lane >> 2);
#pragma unroll
        for (int h = 0; h < 2; h++) {
            int m = m0 + rloc + h * 8;
            if (m < ne) {
                float* orow = g_raw + (size_t)(off + m) * IDIM + n0;
#pragma unroll
                for (int nt = 0; nt < 4; nt++) {
                    int c = n0w + nt * 8 + 2 * (lane & 3);
                    float2 v;
                    v.x = acc[mt][nt][2 * h];
                    v.y = acc[mt][nt][2 * h + 1];
                    *(float2*)(orow + c) = v;
                }
            }
        }
    }
}

// ---------------- up GEMM + SwiGLU: g_act = silu(g_raw) * (x @ Wu) ----------
__global__ __launch_bounds__(256, 2) void up_tc(const float* __restrict__ x) {
    extern __shared__ float sm[];
    const int e = blockIdx.z;
    const int ne = g_off[e + 1] - g_off[e];
    const int m0 = blockIdx.y * BMT;
    if (m0 >= ne) return;
    const int n0 = blockIdx.x * BNT;
    const int off = g_off[e];

    int* rowtok = (int*)sm;
    const int tid = threadIdx.x;
    const int wid = tid >> 5;
    const int lane = tid & 31;
    if (tid < BMT) {
        int m = m0 + tid;
        rowtok[tid] = g_list[off + (m < ne ? m : 0)];
    }
    __syncthreads();

    const float* aptr[4];
#pragma unroll
    for (int i = 0; i < 4; i++) {
        int r = i * 32 + (tid >> 3);
        aptr[i] = x + (size_t)rowtok[r] * HDIM + (tid & 7) * 4;
    }
    const float* bptr = g_wur + (size_t)e * HDIM * IDIM + n0;

    float acc[4][4][4];
#pragma unroll
    for (int i = 0; i < 4; i++)
#pragma unroll
        for (int j = 0; j < 4; j++)
#pragma unroll
            for (int q = 0; q < 4; q++) acc[i][j][q] = 0.f;

    GemmCore::run(sm + 128, aptr, bptr, IDIM, HDIM / KC, tid, wid, lane, acc);

    const int m0w = (wid >> 2) * 64;
    const int n0w = (wid & 3) * 32;
#pragma unroll
    for (int mt = 0; mt < 4; mt++) {
        int rloc = m0w + mt * 16 + (lane >> 2);
#pragma unroll
        for (int h = 0; h < 2; h++) {
            int m = m0 + rloc + h * 8;
            if (m < ne) {
                const float* grow = g_raw + (size_t)(off + m) * IDIM + n0;
                float* orow = g_act + (size_t)(off + m) * IDIM + n0;
#pragma unroll
                for (int nt = 0; nt < 4; nt++) {
                    int c = n0w + nt * 8 + 2 * (lane & 3);
                    float2 gv = *(const float2*)(grow + c);
                    float2 v;
                    v.x = gv.x / (1.f + expf(-gv.x)) * acc[mt][nt][2 * h];
                    v.y = gv.y / (1.f + expf(-gv.y)) * acc[mt][nt][2 * h + 1];
                    *(float2*)(orow + c) = v;
                }
            }
        }
    }
}

// ---------------- down GEMM: g_pairout = wt * (g_act @ Wd) ----------------
__global__ __launch_bounds__(256, 2) void down_tc() {
    extern __shared__ float sm[];
    const int e = blockIdx.z;
    const int ne = g_off[e + 1] - g_off[e];
    const int m0 = blockIdx.y * BMT;
    if (m0 >= ne) return;
    const int n0 = blockIdx.x * BNT;
    const int off = g_off[e];

    const int tid = threadIdx.x;
    const int wid = tid >> 5;
    const int lane = tid & 31;

    const float* aptr[4];
#pragma unroll
    for (int i = 0; i < 4; i++) {
        int r = i * 32 + (tid >> 3);
        int idx = off + m0 + r;
        if (idx >= NPAIR) idx = NPAIR - 1;
        aptr[i] = g_act + (size_t)idx * IDIM + (tid & 7) * 4;
    }
    const float* bptr = g_wdr + (size_t)e * IDIM * HDIM + n0;

    float acc[4][4][4];
#pragma unroll
    for (int i = 0; i < 4; i++)
#pragma unroll
        for (int j = 0; j < 4; j++)
#pragma unroll
            for (int q = 0; q < 4; q++) acc[i][j][q] = 0.f;

    GemmCore::run(sm + 128, aptr, bptr, HDIM, IDIM / KC, tid, wid, lane, acc);

    const int m0w = (wid >> 2) * 64;
    const int n0w = (wid & 3) * 32;
#pragma unroll
    for (int mt = 0; mt < 4; mt++) {
        int rloc = m0w + mt * 16 + (lane >> 2);
#pragma unroll
        for (int h = 0; h < 2; h++) {
            int m = m0 + rloc + h * 8;
            if (m < ne) {
                float wt = g_wt[off + m];
                float* orow = g_pairout + (size_t)(off + m) * HDIM + n0;
#pragma unroll
                for (int nt = 0; nt < 4; nt++) {
                    int c = n0w + nt * 8 + 2 * (lane & 3);
                    float2 v;
                    v.x = wt * acc[mt][nt][2 * h];
                    v.y = wt * acc[mt][nt][2 * h + 1];
                    *(float2*)(orow + c) = v;
                }
            }
        }
    }
}

// out[t, :] = pairout[p0, :] + pairout[p1, :]
__global__ void combine_kernel(float* __restrict__ out) {
    int idx = blockIdx.x * blockDim.x + threadIdx.x;
    int t = idx >> 8;
    int h4 = idx & 255;
    int p0 = g_tokpair[t * 2 + 0];
    int p1 = g_tokpair[t * 2 + 1];
    const float4* po = (const float4*)g_pairout;
    float4 a = po[(size_t)p0 * 256 + h4];
    float4 b = po[(size_t)p1 * 256 + h4];
    float4 r;
    r.x = a.x + b.x; r.y = a.y + b.y; r.z = a.z + b.z; r.w = a.w + b.w;
    ((float4*)out)[idx] = r;
}

// ---------------- launch ----------------
extern "C" void kernel_launch(void* const* d_in, const int* in_sizes, int n_in,
                              void* d_out, int out_size) {
    const float* x  = (const float*)d_in[0];
    const float* gw = (const float*)d_in[1];
    const float* Wg = (const float*)d_in[2];
    const float* Wu = (const float*)d_in[3];
    const float* Wd = (const float*)d_in[4];
    float* out = (float*)d_out;
    float* out_logits = out + (size_t)T_TOK * HDIM;

    cudaFuncSetAttribute(gate_tc, cudaFuncAttributeMaxDynamicSharedMemorySize, GEMM_SMEM);
    cudaFuncSetAttribute(up_tc, cudaFuncAttributeMaxDynamicSharedMemorySize, GEMM_SMEM);
    cudaFuncSetAttribute(down_tc, cudaFuncAttributeMaxDynamicSharedMemorySize, GEMM_SMEM);

    router_kernel<<<T_TOK + RBLKS, 128>>>(x, gw, Wg, Wu, Wd, out_logits);
    scan_kernel<<<1, 1>>>();
    assign_kernel<<<T_TOK / 256, 256>>>();
    gate_tc<<<dim3(IDIM / BNT, NPAIR / BMT, EDIM), 256, GEMM_SMEM>>>(x);
    up_tc<<<dim3(IDIM / BNT, NPAIR / BMT, EDIM), 256, GEMM_SMEM>>>(x);
    down_tc<<<dim3(HDIM / BNT, NPAIR / BMT, EDIM), 256, GEMM_SMEM>>>();
    combine_kernel<<<(T_TOK * HDIM / 4) / 256, 256>>>(out);
}

// round 14
// speedup vs baseline: 1.4869x; 1.2334x over previous
#include <cuda_runtime.h>
#include <cstdint>
#include <math.h>

// Problem constants
#define T_TOK 4096      // B*S
#define HDIM  1024
#define IDIM  2816
#define EDIM  8
#define TOPK  2
#define NPAIR (T_TOK*TOPK)   // 8192

#define KC    32        // K-chunk per stage
#define BMT   128       // CTA M tile
#define BNT   128       // CTA N tile
#define PADA  36        // A smem row pitch (floats)
#define PADB  136       // B smem row pitch (floats)
#define A_FL  (BMT*PADA)   // 4608 floats
#define B_FL  (KC*PADB)    // 4352 floats

// ---------------- scratch (__device__ globals: alloc-free) ----------------
__device__ int   g_cnt[EDIM];        // zero-init at load; scan re-zeroes each call
__device__ int   g_off[EDIM + 1];
__device__ int   g_fill[EDIM];
__device__ int   g_tok_e[NPAIR];
__device__ float g_tok_w[NPAIR];
__device__ int   g_list[NPAIR];
__device__ float g_wt[NPAIR];
__device__ int   g_tokpair[NPAIR];
__device__ float g_raw[(size_t)NPAIR * IDIM];      // raw gate GEMM out
__device__ float g_act[(size_t)NPAIR * IDIM];      // swiglu activations
__device__ float g_pairout[(size_t)NPAIR * HDIM];

// ---------------- helpers ----------------
__device__ __forceinline__ uint32_t f2tf32(float f) {
    uint32_t r;
    asm("cvt.rna.tf32.f32 %0, %1;" : "=r"(r) : "f"(f));
    return r;
}
__device__ __forceinline__ float tf32f(float f) {
    return __uint_as_float(f2tf32(f));
}
__device__ __forceinline__ void mma_tf32(float* d, const uint32_t* a, const uint32_t* b) {
    asm volatile(
        "mma.sync.aligned.m16n8k8.row.col.f32.tf32.tf32.f32 "
        "{%0,%1,%2,%3}, {%4,%5,%6,%7}, {%8,%9}, {%0,%1,%2,%3};"
        : "+f"(d[0]), "+f"(d[1]), "+f"(d[2]), "+f"(d[3])
        : "r"(a[0]), "r"(a[1]), "r"(a[2]), "r"(a[3]), "r"(b[0]), "r"(b[1]));
}
__device__ __forceinline__ uint32_t smem_u32(const void* p) {
    uint32_t a;
    asm("{ .reg .u64 t; cvta.to.shared.u64 t, %1; cvt.u32.u64 %0, t; }" : "=r"(a) : "l"(p));
    return a;
}
__device__ __forceinline__ void cp16(uint32_t dst, const void* src) {
    asm volatile("cp.async.ca.shared.global [%0], [%1], 16;" :: "r"(dst), "l"(src));
}
#define CP_COMMIT() asm volatile("cp.async.commit_group;" ::: "memory")
#define CP_WAIT0()  asm volatile("cp.async.wait_group 0;" ::: "memory")

// ---------------- routing kernels ----------------
__global__ void router_kernel(const float* __restrict__ x,
                              const float* __restrict__ gw,
                              float* __restrict__ out_logits) {
    const int t = blockIdx.x;
    const int tid = threadIdx.x;
    float acc[EDIM];
#pragma unroll
    for (int e = 0; e < EDIM; e++) acc[e] = 0.f;
    const float* xr = x + (size_t)t * HDIM;
    for (int h = tid; h < HDIM; h += 128) {
        float xv = xr[h];
        const float* gr = gw + (size_t)h * EDIM;
#pragma unroll
        for (int e = 0; e < EDIM; e++) acc[e] += xv * gr[e];
    }
    __shared__ float red[EDIM][128];
#pragma unroll
    for (int e = 0; e < EDIM; e++) red[e][tid] = acc[e];
    __syncthreads();
    for (int s = 64; s > 0; s >>= 1) {
        if (tid < s) {
#pragma unroll
            for (int e = 0; e < EDIM; e++) red[e][tid] += red[e][tid + s];
        }
        __syncthreads();
    }
    if (tid == 0) {
        float l[EDIM];
#pragma unroll
        for (int e = 0; e < EDIM; e++) {
            l[e] = red[e][0];
            out_logits[(size_t)t * EDIM + e] = l[e];
        }
        int i0 = 0;
#pragma unroll
        for (int e = 1; e < EDIM; e++) if (l[e] > l[i0]) i0 = e;
        int i1 = -1;
#pragma unroll
        for (int e = 0; e < EDIM; e++) {
            if (e == i0) continue;
            if (i1 < 0 || l[e] > l[i1]) i1 = e;
        }
        float e1 = expf(l[i1] - l[i0]);
        float w0 = 1.f / (1.f + e1);
        float w1 = e1 / (1.f + e1);
        g_tok_e[t * 2 + 0] = i0; g_tok_w[t * 2 + 0] = w0;
        g_tok_e[t * 2 + 1] = i1; g_tok_w[t * 2 + 1] = w1;
        atomicAdd(&g_cnt[i0], 1);
        atomicAdd(&g_cnt[i1], 1);
    }
}

__global__ void scan_kernel() {
    int s = 0;
    for (int e = 0; e < EDIM; e++) {
        g_off[e] = s;
        s += g_cnt[e];
        g_fill[e] = 0;
        g_cnt[e] = 0;
    }
    g_off[EDIM] = s;
}

__global__ void assign_kernel() {
    int t = blockIdx.x * blockDim.x + threadIdx.x;
    if (t >= T_TOK) return;
#pragma unroll
    for (int k = 0; k < TOPK; k++) {
        int e = g_tok_e[t * 2 + k];
        int slot = atomicAdd(&g_fill[e], 1);
        int p = g_off[e] + slot;
        g_list[p] = t;
        g_wt[p] = g_tok_w[t * 2 + k];
        g_tokpair[t * 2 + k] = p;
    }
}

// ============================================================================
// GEMM mainloop core (R8 structure + cp.async double-buffered RAW-f32 A).
// Smem layout: sA0 | sA1 (raw f32, cp.async) | sB (tf32, single stage).
// Loop: stage B(kc) from regs -> sync -> [cp.async A(kc+1), LDG B(kc+1) regs]
//       -> compute(kc) with cvt.rna on A fragments -> wait cp.async -> sync.
// ============================================================================
struct GemmCore {
    static __device__ __forceinline__ void run(
        float* sbuf,
        const float* aptr[4], const float* bptr, size_t ldb,
        int NCH, int tid, int wid, int lane,
        float acc[4][4][4]) {
        const int ac4 = (tid & 7) * 4;
        const int ar  = tid >> 3;            // 0..31
        const int bc4 = (tid & 31) * 4;
        const int br  = tid >> 5;            // 0..7
        const int m0w = (wid >> 2) * 64;
        const int n0w = (wid & 3) * 32;
        const int r0 = lane >> 2;
        const int kq = lane & 3;
        const int nq = lane >> 2;

        const float* bp = bptr + (size_t)br * ldb + bc4;

        float* sA[2] = { sbuf, sbuf + A_FL };
        float* sB = sbuf + 2 * A_FL;
        const uint32_t su = smem_u32(sbuf);
        const uint32_t sAu[2] = { su, su + A_FL * 4 };
        const uint32_t aoff = ((uint32_t)ar * PADA + ac4) * 4;

        float4 vb[4];
        // prologue: cp.async A chunk 0, LDG B chunk 0
#pragma unroll
        for (int i = 0; i < 4; i++)
            cp16(sAu[0] + aoff + (uint32_t)(i * 32 * PADA * 4), aptr[i]);
        CP_COMMIT();
#pragma unroll
        for (int i = 0; i < 4; i++)
            vb[i] = *(const float4*)(bp + (size_t)(i * 8) * ldb);
        CP_WAIT0();

#pragma unroll 1
        for (int kc = 0; kc < NCH; kc++) {
            const int buf = kc & 1;
            const bool more = (kc + 1 < NCH);

            // stage B(kc) from prefetched regs (no LDG dependency)
#pragma unroll
            for (int i = 0; i < 4; i++) {
                float* db = sB + (i * 8 + br) * PADB + bc4;
                db[0] = tf32f(vb[i].x); db[1] = tf32f(vb[i].y);
                db[2] = tf32f(vb[i].z); db[3] = tf32f(vb[i].w);
            }
            __syncthreads();

            // issue next-chunk loads; latency hides under compute
            if (more) {
                const int k0n = (kc + 1) * KC;
#pragma unroll
                for (int i = 0; i < 4; i++)
                    cp16(sAu[buf ^ 1] + aoff + (uint32_t)(i * 32 * PADA * 4),
                         aptr[i] + k0n);
                CP_COMMIT();
                const float* bn = bp + (size_t)k0n * ldb;
#pragma unroll
                for (int i = 0; i < 4; i++)
                    vb[i] = *(const float4*)(bn + (size_t)(i * 8) * ldb);
            }

            // compute on sA[buf] (raw f32 -> cvt at fragment load) and sB
            const float* cA = sA[buf];
#pragma unroll
            for (int k8 = 0; k8 < KC; k8 += 8) {
                uint32_t af[4][4];
#pragma unroll
                for (int mt = 0; mt < 4; mt++) {
                    const float* ab = cA + (m0w + mt * 16 + r0) * PADA + k8 + kq;
                    af[mt][0] = f2tf32(ab[0]);
                    af[mt][1] = f2tf32(ab[8 * PADA]);
                    af[mt][2] = f2tf32(ab[4]);
                    af[mt][3] = f2tf32(ab[8 * PADA + 4]);
                }
#pragma unroll
                for (int nt = 0; nt < 4; nt++) {
                    const float* bb = sB + (k8 + kq) * PADB + n0w + nt * 8 + nq;
                    uint32_t bf[2] = { __float_as_uint(bb[0]), __float_as_uint(bb[4 * PADB]) };
#pragma unroll
                    for (int mt = 0; mt < 4; mt++)
                        mma_tf32(acc[mt][nt], af[mt], bf);
                }
            }
            if (more) CP_WAIT0();
            __syncthreads();
        }
    }
};

#define GEMM_SMEM ((128 + 2 * A_FL + B_FL) * 4)   // rowtok + A0|A1|B

// ---------------- gate GEMM: g_raw = x[rowtok] @ Wg ----------------
__global__ __launch_bounds__(256, 2) void gate_tc(
    const float* __restrict__ x, const float* __restrict__ Wg) {
    extern __shared__ float sm[];
    const int e = blockIdx.z;
    const int ne = g_off[e + 1] - g_off[e];
    const int m0 = blockIdx.y * BMT;
    if (m0 >= ne) return;
    const int n0 = blockIdx.x * BNT;
    const int off = g_off[e];

    int* rowtok = (int*)sm;
    const int tid = threadIdx.x;
    const int wid = tid >> 5;
    const int lane = tid & 31;
    if (tid < BMT) {
        int m = m0 + tid;
        rowtok[tid] = g_list[off + (m < ne ? m : 0)];
    }
    __syncthreads();

    const float* aptr[4];
#pragma unroll
    for (int i = 0; i < 4; i++) {
        int r = i * 32 + (tid >> 3);
        aptr[i] = x + (size_t)rowtok[r] * HDIM + (tid & 7) * 4;
    }
    const float* bptr = Wg + (size_t)e * HDIM * IDIM + n0;

    float acc[4][4][4];
#pragma unroll
    for (int i = 0; i < 4; i++)
#pragma unroll
        for (int j = 0; j < 4; j++)
#pragma unroll
            for (int q = 0; q < 4; q++) acc[i][j][q] = 0.f;

    GemmCore::run(sm + 128, aptr, bptr, IDIM, HDIM / KC, tid, wid, lane, acc);

    const int m0w = (wid >> 2) * 64;
    const int n0w = (wid & 3) * 32;
#pragma unroll
    for (int mt = 0; mt < 4; mt++) {
        int rloc = m0w + mt * 16 + (lane >> 2);
#pragma unroll
        for (int h = 0; h < 2; h++) {
            int m = m0 + rloc + h * 8;
            if (m < ne) {
                float* orow = g_raw + (size_t)(off + m) * IDIM + n0;
#pragma unroll
                for (int nt = 0; nt < 4; nt++) {
                    int c = n0w + nt * 8 + 2 * (lane & 3);
                    float2 v;
                    v.x = acc[mt][nt][2 * h];
                    v.y = acc[mt][nt][2 * h + 1];
                    *(float2*)(orow + c) = v;
                }
            }
        }
    }
}

// ---------------- up GEMM + SwiGLU: g_act = silu(g_raw) * (x @ Wu) ----------
__global__ __launch_bounds__(256, 2) void up_tc(
    const float* __restrict__ x, const float* __restrict__ Wu) {
    extern __shared__ float sm[];
    const int e = blockIdx.z;
    const int ne = g_off[e + 1] - g_off[e];
    const int m0 = blockIdx.y * BMT;
    if (m0 >= ne) return;
    const int n0 = blockIdx.x * BNT;
    const int off = g_off[e];

    int* rowtok = (int*)sm;
    const int tid = threadIdx.x;
    const int wid = tid >> 5;
    const int lane = tid & 31;
    if (tid < BMT) {
        int m = m0 + tid;
        rowtok[tid] = g_list[off + (m < ne ? m : 0)];
    }
    __syncthreads();

    const float* aptr[4];
#pragma unroll
    for (int i = 0; i < 4; i++) {
        int r = i * 32 + (tid >> 3);
        aptr[i] = x + (size_t)rowtok[r] * HDIM + (tid & 7) * 4;
    }
    const float* bptr = Wu + (size_t)e * HDIM * IDIM + n0;

    float acc[4][4][4];
#pragma unroll
    for (int i = 0; i < 4; i++)
#pragma unroll
        for (int j = 0; j < 4; j++)
#pragma unroll
            for (int q = 0; q < 4; q++) acc[i][j][q] = 0.f;

    GemmCore::run(sm + 128, aptr, bptr, IDIM, HDIM / KC, tid, wid, lane, acc);

    const int m0w = (wid >> 2) * 64;
    const int n0w = (wid & 3) * 32;
#pragma unroll
    for (int mt = 0; mt < 4; mt++) {
        int rloc = m0w + mt * 16 + (lane >> 2);
#pragma unroll
        for (int h = 0; h < 2; h++) {
            int m = m0 + rloc + h * 8;
            if (m < ne) {
                const float* grow = g_raw + (size_t)(off + m) * IDIM + n0;
                float* orow = g_act + (size_t)(off + m) * IDIM + n0;
#pragma unroll
                for (int nt = 0; nt < 4; nt++) {
                    int c = n0w + nt * 8 + 2 * (lane & 3);
                    float2 gv = *(const float2*)(grow + c);
                    float2 v;
                    v.x = gv.x / (1.f + expf(-gv.x)) * acc[mt][nt][2 * h];
                    v.y = gv.y / (1.f + expf(-gv.y)) * acc[mt][nt][2 * h + 1];
                    *(float2*)(orow + c) = v;
                }
            }
        }
    }
}

// ---------------- down GEMM: g_pairout = wt * (g_act @ Wd) ----------------
__global__ __launch_bounds__(256, 2) void down_tc(const float* __restrict__ Wd) {
    extern __shared__ float sm[];
    const int e = blockIdx.z;
    const int ne = g_off[e + 1] - g_off[e];
    const int m0 = blockIdx.y * BMT;
    if (m0 >= ne) return;
    const int n0 = blockIdx.x * BNT;
    const int off = g_off[e];

    const int tid = threadIdx.x;
    const int wid = tid >> 5;
    const int lane = tid & 31;

    const float* aptr[4];
#pragma unroll
    for (int i = 0; i < 4; i++) {
        int r = i * 32 + (tid >> 3);
        int idx = off + m0 + r;
        if (idx >= NPAIR) idx = NPAIR - 1;
        aptr[i] = g_act + (size_t)idx * IDIM + (tid & 7) * 4;
    }
    const float* bptr = Wd + (size_t)e * IDIM * HDIM + n0;

    float acc[4][4][4];
#pragma unroll
    for (int i = 0; i < 4; i++)
#pragma unroll
        for (int j = 0; j < 4; j++)
#pragma unroll
            for (int q = 0; q < 4; q++) acc[i][j][q] = 0.f;

    GemmCore::run(sm + 128, aptr, bptr, HDIM, IDIM / KC, tid, wid, lane, acc);

    const int m0w = (wid >> 2) * 64;
    const int n0w = (wid & 3) * 32;
#pragma unroll
    for (int mt = 0; mt < 4; mt++) {
        int rloc = m0w + mt * 16 + (lane >> 2);
#pragma unroll
        for (int h = 0; h < 2; h++) {
            int m = m0 + rloc + h * 8;
            if (m < ne) {
                float wt = g_wt[off + m];
                float* orow = g_pairout + (size_t)(off + m) * HDIM + n0;
#pragma unroll
                for (int nt = 0; nt < 4; nt++) {
                    int c = n0w + nt * 8 + 2 * (lane & 3);
                    float2 v;
                    v.x = wt * acc[mt][nt][2 * h];
                    v.y = wt * acc[mt][nt][2 * h + 1];
                    *(float2*)(orow + c) = v;
                }
            }
        }
    }
}

// out[t, :] = pairout[p0, :] + pairout[p1, :]
__global__ void combine_kernel(float* __restrict__ out) {
    int idx = blockIdx.x * blockDim.x + threadIdx.x;
    int t = idx >> 8;
    int h4 = idx & 255;
    int p0 = g_tokpair[t * 2 + 0];
    int p1 = g_tokpair[t * 2 + 1];
    const float4* po = (const float4*)g_pairout;
    float4 a = po[(size_t)p0 * 256 + h4];
    float4 b = po[(size_t)p1 * 256 + h4];
    float4 r;
    r.x = a.x + b.x; r.y = a.y + b.y; r.z = a.z + b.z; r.w = a.w + b.w;
    ((float4*)out)[idx] = r;
}

// ---------------- launch ----------------
extern "C" void kernel_launch(void* const* d_in, const int* in_sizes, int n_in,
                              void* d_out, int out_size) {
    const float* x  = (const float*)d_in[0];
    const float* gw = (const float*)d_in[1];
    const float* Wg = (const float*)d_in[2];
    const float* Wu = (const float*)d_in[3];
    const float* Wd = (const float*)d_in[4];
    float* out = (float*)d_out;
    float* out_logits = out + (size_t)T_TOK * HDIM;

    cudaFuncSetAttribute(gate_tc, cudaFuncAttributeMaxDynamicSharedMemorySize, GEMM_SMEM);
    cudaFuncSetAttribute(up_tc, cudaFuncAttributeMaxDynamicSharedMemorySize, GEMM_SMEM);
    cudaFuncSetAttribute(down_tc, cudaFuncAttributeMaxDynamicSharedMemorySize, GEMM_SMEM);

    router_kernel<<<T_TOK, 128>>>(x, gw, out_logits);
    scan_kernel<<<1, 1>>>();
    assign_kernel<<<T_TOK / 256, 256>>>();
    gate_tc<<<dim3(IDIM / BNT, NPAIR / BMT, EDIM), 256, GEMM_SMEM>>>(x, Wg);
    up_tc<<<dim3(IDIM / BNT, NPAIR / BMT, EDIM), 256, GEMM_SMEM>>>(x, Wu);
    down_tc<<<dim3(HDIM / BNT, NPAIR / BMT, EDIM), 256, GEMM_SMEM>>>(Wd);
    combine_kernel<<<(T_TOK * HDIM / 4) / 256, 256>>>(out);
}

// round 15
// speedup vs baseline: 1.6457x; 1.1068x over previous
#include <cuda_runtime.h>
#include <cstdint>
#include <math.h>

// Problem constants
#define T_TOK 4096      // B*S
#define HDIM  1024
#define IDIM  2816
#define EDIM  8
#define TOPK  2
#define NPAIR (T_TOK*TOPK)   // 8192

#define KC    32        // K-chunk per stage
#define BMT   128       // CTA M tile
#define BNT   128       // CTA N tile
#define PADA  36        // A smem row pitch (floats)
#define PADB  136       // B smem row pitch (floats)
#define A_FL  (BMT*PADA)   // 4608 floats
#define B_FL  (KC*PADB)    // 4352 floats

// x pre-rounding (fused into router launch)
#define XQ (T_TOK*HDIM/4)      // 1,048,576 float4
#define XQ_PER_BLK (128*8)     // 1024 float4 per block
#define XBLKS (XQ/XQ_PER_BLK)  // 1024

// ---------------- scratch (__device__ globals: alloc-free) ----------------
__device__ int   g_cnt[EDIM];        // zero-init at load; scan re-zeroes each call
__device__ int   g_off[EDIM + 1];
__device__ int   g_fill[EDIM];
__device__ int   g_tok_e[NPAIR];
__device__ float g_tok_w[NPAIR];
__device__ int   g_list[NPAIR];
__device__ float g_wt[NPAIR];
__device__ int   g_tokpair[NPAIR];
__device__ float g_xr[(size_t)T_TOK * HDIM];       // tf32-rounded x, 16.8 MB
__device__ float g_raw[(size_t)NPAIR * IDIM];      // raw gate GEMM out
__device__ float g_act[(size_t)NPAIR * IDIM];      // swiglu acts (tf32-rounded)
__device__ float g_pairout[(size_t)NPAIR * HDIM];

// ---------------- helpers ----------------
__device__ __forceinline__ uint32_t f2tf32(float f) {
    uint32_t r;
    asm("cvt.rna.tf32.f32 %0, %1;" : "=r"(r) : "f"(f));
    return r;
}
__device__ __forceinline__ float tf32f(float f) {
    return __uint_as_float(f2tf32(f));
}
__device__ __forceinline__ void mma_tf32(float* d, const uint32_t* a, const uint32_t* b) {
    asm volatile(
        "mma.sync.aligned.m16n8k8.row.col.f32.tf32.tf32.f32 "
        "{%0,%1,%2,%3}, {%4,%5,%6,%7}, {%8,%9}, {%0,%1,%2,%3};"
        : "+f"(d[0]), "+f"(d[1]), "+f"(d[2]), "+f"(d[3])
        : "r"(a[0]), "r"(a[1]), "r"(a[2]), "r"(a[3]), "r"(b[0]), "r"(b[1]));
}
__device__ __forceinline__ uint32_t smem_u32(const void* p) {
    uint32_t a;
    asm("{ .reg .u64 t; cvta.to.shared.u64 t, %1; cvt.u32.u64 %0, t; }" : "=r"(a) : "l"(p));
    return a;
}
__device__ __forceinline__ void cp16(uint32_t dst, const void* src) {
    asm volatile("cp.async.ca.shared.global [%0], [%1], 16;" :: "r"(dst), "l"(src));
}
#define CP_COMMIT() asm volatile("cp.async.commit_group;" ::: "memory")
#define CP_WAIT0()  asm volatile("cp.async.wait_group 0;" ::: "memory")

// ---------------- router + x pre-rounding (fused launch #1) ----------------
__global__ void router_kernel(const float* __restrict__ x,
                              const float* __restrict__ gw,
                              float* __restrict__ out_logits) {
    if (blockIdx.x >= T_TOK) {
        // x pre-round duty: g_xr = tf32(x)
        int b = blockIdx.x - T_TOK;
        const float4* src = (const float4*)x;
        float4* dst = (float4*)g_xr;
        int base = b * XQ_PER_BLK + threadIdx.x;
#pragma unroll
        for (int it = 0; it < 8; it++) {
            int i = base + it * 128;
            float4 v = src[i];
            v.x = tf32f(v.x); v.y = tf32f(v.y);
            v.z = tf32f(v.z); v.w = tf32f(v.w);
            dst[i] = v;
        }
        return;
    }

    const int t = blockIdx.x;
    const int tid = threadIdx.x;
    float acc[EDIM];
#pragma unroll
    for (int e = 0; e < EDIM; e++) acc[e] = 0.f;
    const float* xr = x + (size_t)t * HDIM;
    for (int h = tid; h < HDIM; h += 128) {
        float xv = xr[h];
        const float* gr = gw + (size_t)h * EDIM;
#pragma unroll
        for (int e = 0; e < EDIM; e++) acc[e] += xv * gr[e];
    }
    __shared__ float red[EDIM][128];
#pragma unroll
    for (int e = 0; e < EDIM; e++) red[e][tid] = acc[e];
    __syncthreads();
    for (int s = 64; s > 0; s >>= 1) {
        if (tid < s) {
#pragma unroll
            for (int e = 0; e < EDIM; e++) red[e][tid] += red[e][tid + s];
        }
        __syncthreads();
    }
    if (tid == 0) {
        float l[EDIM];
#pragma unroll
        for (int e = 0; e < EDIM; e++) {
            l[e] = red[e][0];
            out_logits[(size_t)t * EDIM + e] = l[e];
        }
        int i0 = 0;
#pragma unroll
        for (int e = 1; e < EDIM; e++) if (l[e] > l[i0]) i0 = e;
        int i1 = -1;
#pragma unroll
        for (int e = 0; e < EDIM; e++) {
            if (e == i0) continue;
            if (i1 < 0 || l[e] > l[i1]) i1 = e;
        }
        float e1 = expf(l[i1] - l[i0]);
        float w0 = 1.f / (1.f + e1);
        float w1 = e1 / (1.f + e1);
        g_tok_e[t * 2 + 0] = i0; g_tok_w[t * 2 + 0] = w0;
        g_tok_e[t * 2 + 1] = i1; g_tok_w[t * 2 + 1] = w1;
        atomicAdd(&g_cnt[i0], 1);
        atomicAdd(&g_cnt[i1], 1);
    }
}

__global__ void scan_kernel() {
    int s = 0;
    for (int e = 0; e < EDIM; e++) {
        g_off[e] = s;
        s += g_cnt[e];
        g_fill[e] = 0;
        g_cnt[e] = 0;
    }
    g_off[EDIM] = s;
}

__global__ void assign_kernel() {
    int t = blockIdx.x * blockDim.x + threadIdx.x;
    if (t >= T_TOK) return;
#pragma unroll
    for (int k = 0; k < TOPK; k++) {
        int e = g_tok_e[t * 2 + k];
        int slot = atomicAdd(&g_fill[e], 1);
        int p = g_off[e] + slot;
        g_list[p] = t;
        g_wt[p] = g_tok_w[t * 2 + k];
        g_tokpair[t * 2 + k] = p;
    }
}

// ============================================================================
// GEMM mainloop core: cp.async double-buffered PRE-ROUNDED A (no cvt in loop),
// B via reg-prefetch LDG -> cvt -> STS (single stage).
// Loop: stage B(kc) from regs -> sync -> [cp.async A(kc+1), LDG B(kc+1) regs]
//       -> compute(kc), plain fragment loads -> wait cp.async -> sync.
// aptr sources MUST already be tf32-rounded (g_xr / g_act).
// ============================================================================
struct GemmCore {
    static __device__ __forceinline__ void run(
        float* sbuf,
        const float* aptr[4], const float* bptr, size_t ldb,
        int NCH, int tid, int wid, int lane,
        float acc[4][4][4]) {
        const int ac4 = (tid & 7) * 4;
        const int ar  = tid >> 3;            // 0..31
        const int bc4 = (tid & 31) * 4;
        const int br  = tid >> 5;            // 0..7
        const int m0w = (wid >> 2) * 64;
        const int n0w = (wid & 3) * 32;
        const int r0 = lane >> 2;
        const int kq = lane & 3;
        const int nq = lane >> 2;

        const float* bp = bptr + (size_t)br * ldb + bc4;

        float* sA[2] = { sbuf, sbuf + A_FL };
        float* sB = sbuf + 2 * A_FL;
        const uint32_t su = smem_u32(sbuf);
        const uint32_t sAu[2] = { su, su + A_FL * 4 };
        const uint32_t aoff = ((uint32_t)ar * PADA + ac4) * 4;

        float4 vb[4];
        // prologue: cp.async A chunk 0, LDG B chunk 0
#pragma unroll
        for (int i = 0; i < 4; i++)
            cp16(sAu[0] + aoff + (uint32_t)(i * 32 * PADA * 4), aptr[i]);
        CP_COMMIT();
#pragma unroll
        for (int i = 0; i < 4; i++)
            vb[i] = *(const float4*)(bp + (size_t)(i * 8) * ldb);
        CP_WAIT0();

#pragma unroll 1
        for (int kc = 0; kc < NCH; kc++) {
            const int buf = kc & 1;
            const bool more = (kc + 1 < NCH);

            // stage B(kc) from prefetched regs (cvt here, off the critical path)
#pragma unroll
            for (int i = 0; i < 4; i++) {
                float* db = sB + (i * 8 + br) * PADB + bc4;
                db[0] = tf32f(vb[i].x); db[1] = tf32f(vb[i].y);
                db[2] = tf32f(vb[i].z); db[3] = tf32f(vb[i].w);
            }
            __syncthreads();

            // issue next-chunk loads; latency hides under compute
            if (more) {
                const int k0n = (kc + 1) * KC;
#pragma unroll
                for (int i = 0; i < 4; i++)
                    cp16(sAu[buf ^ 1] + aoff + (uint32_t)(i * 32 * PADA * 4),
                         aptr[i] + k0n);
                CP_COMMIT();
                const float* bn = bp + (size_t)k0n * ldb;
#pragma unroll
                for (int i = 0; i < 4; i++)
                    vb[i] = *(const float4*)(bn + (size_t)(i * 8) * ldb);
            }

            // compute on sA[buf] (pre-rounded: plain loads, no cvt) and sB
            const float* cA = sA[buf];
#pragma unroll
            for (int k8 = 0; k8 < KC; k8 += 8) {
                uint32_t af[4][4];
#pragma unroll
                for (int mt = 0; mt < 4; mt++) {
                    const float* ab = cA + (m0w + mt * 16 + r0) * PADA + k8 + kq;
                    af[mt][0] = __float_as_uint(ab[0]);
                    af[mt][1] = __float_as_uint(ab[8 * PADA]);
                    af[mt][2] = __float_as_uint(ab[4]);
                    af[mt][3] = __float_as_uint(ab[8 * PADA + 4]);
                }
#pragma unroll
                for (int nt = 0; nt < 4; nt++) {
                    const float* bb = sB + (k8 + kq) * PADB + n0w + nt * 8 + nq;
                    uint32_t bf[2] = { __float_as_uint(bb[0]), __float_as_uint(bb[4 * PADB]) };
#pragma unroll
                    for (int mt = 0; mt < 4; mt++)
                        mma_tf32(acc[mt][nt], af[mt], bf);
                }
            }
            if (more) CP_WAIT0();
            __syncthreads();
        }
    }
};

#define GEMM_SMEM ((128 + 2 * A_FL + B_FL) * 4)   // rowtok + A0|A1|B

// ---------------- gate GEMM: g_raw = xr[rowtok] @ Wg ----------------
__global__ __launch_bounds__(256, 2) void gate_tc(const float* __restrict__ Wg) {
    extern __shared__ float sm[];
    const int e = blockIdx.z;
    const int ne = g_off[e + 1] - g_off[e];
    const int m0 = blockIdx.y * BMT;
    if (m0 >= ne) return;
    const int n0 = blockIdx.x * BNT;
    const int off = g_off[e];

    int* rowtok = (int*)sm;
    const int tid = threadIdx.x;
    const int wid = tid >> 5;
    const int lane = tid & 31;
    if (tid < BMT) {
        int m = m0 + tid;
        rowtok[tid] = g_list[off + (m < ne ? m : 0)];
    }
    __syncthreads();

    const float* aptr[4];
#pragma unroll
    for (int i = 0; i < 4; i++) {
        int r = i * 32 + (tid >> 3);
        aptr[i] = g_xr + (size_t)rowtok[r] * HDIM + (tid & 7) * 4;
    }
    const float* bptr = Wg + (size_t)e * HDIM * IDIM + n0;

    float acc[4][4][4];
#pragma unroll
    for (int i = 0; i < 4; i++)
#pragma unroll
        for (int j = 0; j < 4; j++)
#pragma unroll
            for (int q = 0; q < 4; q++) acc[i][j][q] = 0.f;

    GemmCore::run(sm + 128, aptr, bptr, IDIM, HDIM / KC, tid, wid, lane, acc);

    const int m0w = (wid >> 2) * 64;
    const int n0w = (wid & 3) * 32;
#pragma unroll
    for (int mt = 0; mt < 4; mt++) {
        int rloc = m0w + mt * 16 + (lane >> 2);
#pragma unroll
        for (int h = 0; h < 2; h++) {
            int m = m0 + rloc + h * 8;
            if (m < ne) {
                float* orow = g_raw + (size_t)(off + m) * IDIM + n0;
#pragma unroll
                for (int nt = 0; nt < 4; nt++) {
                    int c = n0w + nt * 8 + 2 * (lane & 3);
                    float2 v;
                    v.x = acc[mt][nt][2 * h];
                    v.y = acc[mt][nt][2 * h + 1];
                    *(float2*)(orow + c) = v;
                }
            }
        }
    }
}

// ---- up GEMM + SwiGLU: g_act = tf32(silu(g_raw) * (xr @ Wu)) ----
__global__ __launch_bounds__(256, 2) void up_tc(const float* __restrict__ Wu) {
    extern __shared__ float sm[];
    const int e = blockIdx.z;
    const int ne = g_off[e + 1] - g_off[e];
    const int m0 = blockIdx.y * BMT;
    if (m0 >= ne) return;
    const int n0 = blockIdx.x * BNT;
    const int off = g_off[e];

    int* rowtok = (int*)sm;
    const int tid = threadIdx.x;
    const int wid = tid >> 5;
    const int lane = tid & 31;
    if (tid < BMT) {
        int m = m0 + tid;
        rowtok[tid] = g_list[off + (m < ne ? m : 0)];
    }
    __syncthreads();

    const float* aptr[4];
#pragma unroll
    for (int i = 0; i < 4; i++) {
        int r = i * 32 + (tid >> 3);
        aptr[i] = g_xr + (size_t)rowtok[r] * HDIM + (tid & 7) * 4;
    }
    const float* bptr = Wu + (size_t)e * HDIM * IDIM + n0;

    float acc[4][4][4];
#pragma unroll
    for (int i = 0; i < 4; i++)
#pragma unroll
        for (int j = 0; j < 4; j++)
#pragma unroll
            for (int q = 0; q < 4; q++) acc[i][j][q] = 0.f;

    GemmCore::run(sm + 128, aptr, bptr, IDIM, HDIM / KC, tid, wid, lane, acc);

    const int m0w = (wid >> 2) * 64;
    const int n0w = (wid & 3) * 32;
#pragma unroll
    for (int mt = 0; mt < 4; mt++) {
        int rloc = m0w + mt * 16 + (lane >> 2);
#pragma unroll
        for (int h = 0; h < 2; h++) {
            int m = m0 + rloc + h * 8;
            if (m < ne) {
                const float* grow = g_raw + (size_t)(off + m) * IDIM + n0;
                float* orow = g_act + (size_t)(off + m) * IDIM + n0;
#pragma unroll
                for (int nt = 0; nt < 4; nt++) {
                    int c = n0w + nt * 8 + 2 * (lane & 3);
                    float2 gv = *(const float2*)(grow + c);
                    float2 v;
                    // tf32-round at write: identical value to rounding at
                    // down_tc staging, so rel_err must not change.
                    v.x = tf32f(gv.x / (1.f + expf(-gv.x)) * acc[mt][nt][2 * h]);
                    v.y = tf32f(gv.y / (1.f + expf(-gv.y)) * acc[mt][nt][2 * h + 1]);
                    *(float2*)(orow + c) = v;
                }
            }
        }
    }
}

// ---------------- down GEMM: g_pairout = wt * (g_act @ Wd) ----------------
__global__ __launch_bounds__(256, 2) void down_tc(const float* __restrict__ Wd) {
    extern __shared__ float sm[];
    const int e = blockIdx.z;
    const int ne = g_off[e + 1] - g_off[e];
    const int m0 = blockIdx.y * BMT;
    if (m0 >= ne) return;
    const int n0 = blockIdx.x * BNT;
    const int off = g_off[e];

    const int tid = threadIdx.x;
    const int wid = tid >> 5;
    const int lane = tid & 31;

    const float* aptr[4];
#pragma unroll
    for (int i = 0; i < 4; i++) {
        int r = i * 32 + (tid >> 3);
        int idx = off + m0 + r;
        if (idx >= NPAIR) idx = NPAIR - 1;
        aptr[i] = g_act + (size_t)idx * IDIM + (tid & 7) * 4;   // pre-rounded
    }
    const float* bptr = Wd + (size_t)e * IDIM * HDIM + n0;

    float acc[4][4][4];
#pragma unroll
    for (int i = 0; i < 4; i++)
#pragma unroll
        for (int j = 0; j < 4; j++)
#pragma unroll
            for (int q = 0; q < 4; q++) acc[i][j][q] = 0.f;

    GemmCore::run(sm + 128, aptr, bptr, HDIM, IDIM / KC, tid, wid, lane, acc);

    const int m0w = (wid >> 2) * 64;
    const int n0w = (wid & 3) * 32;
#pragma unroll
    for (int mt = 0; mt < 4; mt++) {
        int rloc = m0w + mt * 16 + (lane >> 2);
#pragma unroll
        for (int h = 0; h < 2; h++) {
            int m = m0 + rloc + h * 8;
            if (m < ne) {
                float wt = g_wt[off + m];
                float* orow = g_pairout + (size_t)(off + m) * HDIM + n0;
#pragma unroll
                for (int nt = 0; nt < 4; nt++) {
                    int c = n0w + nt * 8 + 2 * (lane & 3);
                    float2 v;
                    v.x = wt * acc[mt][nt][2 * h];
                    v.y = wt * acc[mt][nt][2 * h + 1];
                    *(float2*)(orow + c) = v;
                }
            }
        }
    }
}

// out[t, :] = pairout[p0, :] + pairout[p1, :]
__global__ void combine_kernel(float* __restrict__ out) {
    int idx = blockIdx.x * blockDim.x + threadIdx.x;
    int t = idx >> 8;
    int h4 = idx & 255;
    int p0 = g_tokpair[t * 2 + 0];
    int p1 = g_tokpair[t * 2 + 1];
    const float4* po = (const float4*)g_pairout;
    float4 a = po[(size_t)p0 * 256 + h4];
    float4 b = po[(size_t)p1 * 256 + h4];
    float4 r;
    r.x = a.x + b.x; r.y = a.y + b.y; r.z = a.z + b.z; r.w = a.w + b.w;
    ((float4*)out)[idx] = r;
}

// ---------------- launch ----------------
extern "C" void kernel_launch(void* const* d_in, const int* in_sizes, int n_in,
                              void* d_out, int out_size) {
    const float* x  = (const float*)d_in[0];
    const float* gw = (const float*)d_in[1];
    const float* Wg = (const float*)d_in[2];
    const float* Wu = (const float*)d_in[3];
    const float* Wd = (const float*)d_in[4];
    float* out = (float*)d_out;
    float* out_logits = out + (size_t)T_TOK * HDIM;

    cudaFuncSetAttribute(gate_tc, cudaFuncAttributeMaxDynamicSharedMemorySize, GEMM_SMEM);
    cudaFuncSetAttribute(up_tc, cudaFuncAttributeMaxDynamicSharedMemorySize, GEMM_SMEM);
    cudaFuncSetAttribute(down_tc, cudaFuncAttributeMaxDynamicSharedMemorySize, GEMM_SMEM);

    router_kernel<<<T_TOK + XBLKS, 128>>>(x, gw, out_logits);
    scan_kernel<<<1, 1>>>();
    assign_kernel<<<T_TOK / 256, 256>>>();
    gate_tc<<<dim3(IDIM / BNT, NPAIR / BMT, EDIM), 256, GEMM_SMEM>>>(Wg);
    up_tc<<<dim3(IDIM / BNT, NPAIR / BMT, EDIM), 256, GEMM_SMEM>>>(Wu);
    down_tc<<<dim3(HDIM / BNT, NPAIR / BMT, EDIM), 256, GEMM_SMEM>>>(Wd);
    combine_kernel<<<(T_TOK * HDIM / 4) / 256, 256>>>(out);
}